// round 13
// baseline (speedup 1.0000x reference)
#include <cuda_runtime.h>
#include <cuda_fp16.h>
#include <cstdint>
#include <math.h>

// ---------------------------------------------------------------------------
// SimpleConvRNN fused kernel for GB300 (sm_103a) — round 13.
// R12 with the one-instruction fix: L2's W2 B-operand must use TRANS ldmatrix
// ([k][out] memory -> B-fragment (n=l/4, k=2(l%4))). Non-trans gave the
// transposed fragment -> rel_err 1.3. Everything else identical to R12:
//  - 768 thr, 24 warps = 4og x 6pg, mma.sync fp16 32x32, named-barrier groups
//  - zero-skip of L0 lower half when use_memory==0
//  - L2 operand swap (A=X, B=W2) -> coalesced sector-aligned STG.32
//  - cooperative balanced staging + pre-barrier LDG prefetch
// ---------------------------------------------------------------------------

namespace {
constexpr int kB   = 32;
constexpr int kHW  = 6144;
constexpr int kTP  = 192;                   // pixels per tile (6 px-groups x 32)
constexpr int kTilesPerB = 32;
constexpr int kNTiles = kB * kTilesPerB;    // 1024
constexpr int kTHREADS = 768;

constexpr int kLDW  = 136;                  // W0/W1 pitch (halves)
constexpr int kLDW2 = 72;                   // W2 pitch (halves)
constexpr int kLDX  = 200;                  // xs pitch (halves)

constexpr int W0B = 0;
constexpr int W1B = W0B + 128 * kLDW * 2;   // 34816
constexpr int W2B = W1B + 128 * kLDW * 2;   // 69632
constexpr int X0B = W2B + 128 * kLDW2 * 2;  // 88064
constexpr int X1B = X0B + 128 * kLDX * 2;   // 139264
constexpr size_t SMEM_BYTES = X1B + 128 * kLDX * 2;  // 190464 B
}

__device__ __forceinline__ uint32_t smem_u32(const void* p) {
    uint32_t a;
    asm("{ .reg .u64 t; cvta.to.shared.u64 t, %1; cvt.u32.u64 %0, t; }"
        : "=r"(a) : "l"(p));
    return a;
}
__device__ __forceinline__ void ldsm4t(uint32_t* r, uint32_t addr) {
    asm volatile("ldmatrix.sync.aligned.m8n8.x4.trans.shared.b16 "
                 "{%0,%1,%2,%3}, [%4];"
                 : "=r"(r[0]), "=r"(r[1]), "=r"(r[2]), "=r"(r[3]) : "r"(addr));
}
__device__ __forceinline__ void mma16816(float c[4], const uint32_t* a,
                                         const uint32_t b0, const uint32_t b1) {
    asm volatile(
        "mma.sync.aligned.m16n8k16.row.col.f32.f16.f16.f32 "
        "{%0,%1,%2,%3}, {%4,%5,%6,%7}, {%8,%9}, {%0,%1,%2,%3};"
        : "+f"(c[0]), "+f"(c[1]), "+f"(c[2]), "+f"(c[3])
        : "r"(a[0]), "r"(a[1]), "r"(a[2]), "r"(a[3]), "r"(b0), "r"(b1));
}
__device__ __forceinline__ void mma16816_p(float c[4],
                                           uint32_t a0, uint32_t a1,
                                           uint32_t a2, uint32_t a3,
                                           uint32_t b0, uint32_t b1) {
    asm volatile(
        "mma.sync.aligned.m16n8k16.row.col.f32.f16.f16.f32 "
        "{%0,%1,%2,%3}, {%4,%5,%6,%7}, {%8,%9}, {%0,%1,%2,%3};"
        : "+f"(c[0]), "+f"(c[1]), "+f"(c[2]), "+f"(c[3])
        : "r"(a0), "r"(a1), "r"(a2), "r"(a3), "r"(b0), "r"(b1));
}
__device__ __forceinline__ uint32_t h2pack(float a, float b) {
    __half2 h = __floats2half2_rn(a, b);
    return *(uint32_t*)&h;
}
__device__ __forceinline__ void st_half4(__half* p, float a, float b,
                                         float c, float d) {
    uint2 v;
    v.x = h2pack(a, b);
    v.y = h2pack(c, d);
    *(uint2*)p = v;
}
#define GBAR(pg) asm volatile("bar.sync %0, 128;" :: "r"(1 + (pg)) : "memory")

__device__ float g_xf[kB * 16];
__device__ int   g_use[kB];
__device__ int   g_midx[kB];

// ---------------------------------------------------------------------------
__global__ void prep_kernel(const float* __restrict__ prev_ext,
                            const float* __restrict__ cur_ext,
                            const int*   __restrict__ memory_idx,
                            const unsigned char* __restrict__ use_raw) {
    int b = threadIdx.x;
    if (b >= kB) return;

    const unsigned int* w32 = (const unsigned int*)use_raw;
    bool int_layout = true, float_layout = true;
    #pragma unroll
    for (int i = 0; i < 8; i++) {
        unsigned int v = w32[i];
        if (v != 0u && v != 1u)          int_layout = false;
        if (v != 0u && v != 0x3f800000u) float_layout = false;
    }
    int use;
    if (int_layout || float_layout) use = (w32[b] != 0u) ? 1 : 0;
    else                            use = use_raw[b] ? 1 : 0;
    g_use[b] = use;
    int m = memory_idx[b];
    g_midx[b] = m;

    float A[4][8];
    #pragma unroll
    for (int r = 0; r < 4; r++)
        #pragma unroll
        for (int c = 0; c < 4; c++) {
            A[r][c]     = use ? prev_ext[(size_t)m * 16 + r * 4 + c]
                              : (r == c ? 1.f : 0.f);
            A[r][c + 4] = (r == c) ? 1.f : 0.f;
        }
    for (int col = 0; col < 4; col++) {
        int piv = col;
        float best = fabsf(A[col][col]);
        for (int r = col + 1; r < 4; r++) {
            float v = fabsf(A[r][col]);
            if (v > best) { best = v; piv = r; }
        }
        if (piv != col)
            for (int j = 0; j < 8; j++) {
                float t = A[col][j]; A[col][j] = A[piv][j]; A[piv][j] = t;
            }
        float inv = 1.f / A[col][col];
        for (int j = 0; j < 8; j++) A[col][j] *= inv;
        for (int r = 0; r < 4; r++) {
            if (r == col) continue;
            float f = A[r][col];
            for (int j = 0; j < 8; j++) A[r][j] -= f * A[col][j];
        }
    }
    #pragma unroll
    for (int i = 0; i < 4; i++)
        #pragma unroll
        for (int j = 0; j < 4; j++) {
            float s = 0.f;
            #pragma unroll
            for (int k = 0; k < 4; k++)
                s += cur_ext[(size_t)b * 16 + i * 4 + k] * A[k][4 + j];
            g_xf[b * 16 + i * 4 + j] = s;
        }
}

// ---------------------------------------------------------------------------
// 32out x 32px layer slice, ksteps k-iterations. Epilogue bias+relu+fp16 -> STS.
__device__ __forceinline__ void layer_gemm32(
    uint32_t aW, uint32_t aB, int ksteps, const float bl[4],
    uint32_t xw, int out0, int pxcol, int r, int col2)
{
    float c[8][4];
    #pragma unroll
    for (int i = 0; i < 8; i++)
        #pragma unroll
        for (int j = 0; j < 4; j++) c[i][j] = 0.f;

    #pragma unroll 4
    for (int k = 0; k < ksteps; k++) {
        uint32_t a0[4], a1[4], b0[4], b1[4];
        ldsm4t(a0, aW);
        ldsm4t(a1, aW + 32);
        ldsm4t(b0, aB);
        ldsm4t(b1, aB + 32);
        mma16816(c[0], a0, b0[0], b0[1]);
        mma16816(c[1], a0, b0[2], b0[3]);
        mma16816(c[2], a0, b1[0], b1[1]);
        mma16816(c[3], a0, b1[2], b1[3]);
        mma16816(c[4], a1, b0[0], b0[1]);
        mma16816(c[5], a1, b0[2], b0[3]);
        mma16816(c[6], a1, b1[0], b1[1]);
        mma16816(c[7], a1, b1[2], b1[3]);
        aW += 16 * kLDW * 2;
        aB += 16 * kLDX * 2;
    }

    #pragma unroll
    for (int f = 0; f < 2; f++) {
        float bhi = bl[2 * f], blo = bl[2 * f + 1];
        int row = out0 + 16 * f + r;
        #pragma unroll
        for (int p = 0; p < 4; p++) {
            const float* cc = c[f * 4 + p];
            uint32_t h01 = h2pack(fmaxf(cc[0] + bhi, 0.f),
                                  fmaxf(cc[1] + bhi, 0.f));
            uint32_t h23 = h2pack(fmaxf(cc[2] + blo, 0.f),
                                  fmaxf(cc[3] + blo, 0.f));
            uint32_t addr = xw + (uint32_t)(row * kLDX + pxcol + 8 * p + col2) * 2;
            asm volatile("st.shared.b32 [%0], %1;" :: "r"(addr), "r"(h01));
            asm volatile("st.shared.b32 [%0], %1;"
                         :: "r"(addr + 8 * kLDX * 2), "r"(h23));
        }
    }
}

// ---------------------------------------------------------------------------
__global__ void __launch_bounds__(kTHREADS, 1)
fused_kernel(const float* __restrict__ img,
             const float* __restrict__ mem,
             const float* __restrict__ Ws,
             const float* __restrict__ bs,
             float* __restrict__ out) {
    extern __shared__ char smc[];
    const uint32_t sb = smem_u32(smc);
    __half* W0h = (__half*)(smc + W0B);
    __half* W1h = (__half*)(smc + W1B);
    __half* W2h = (__half*)(smc + W2B);
    __half* xs0 = (__half*)(smc + X0B);

    const int tid  = threadIdx.x;
    const int wid  = tid >> 5;
    const int lane = tid & 31;
    const int r    = lane >> 2;
    const int col2 = (lane & 3) * 2;

    // ---- one-time weight staging (transposed [k][out], fp16) ----
    for (int i = tid; i < 128 * 128; i += kTHREADS) {
        int o = i >> 7, k = i & 127;
        W0h[k * kLDW + o] = __float2half_rn(Ws[o * 128 + k]);
        W1h[k * kLDW + o] = __float2half_rn(Ws[16384 + o * 128 + k]);
    }
    for (int i = tid; i < 64 * 128; i += kTHREADS) {
        int o = i >> 7, k = i & 127;
        W2h[k * kLDW2 + o] = __float2half_rn(Ws[2 * 16384 + (64 + o) * 128 + k]);
    }

    // ---- warp tiling: og = out-group (32 ch), pg = px-group (32 px) ----
    const int og    = wid & 3;
    const int pg    = wid >> 2;                // 0..5
    const int out0  = og * 32;
    const int px0   = pg * 32;
    const int out20 = og * 16;                 // L2 out block (0..63)
    const int glt   = og * 32 + lane;          // group-local tid 0..127
    float bL0[4], bL1[4];
    #pragma unroll
    for (int j = 0; j < 4; j++) {
        bL0[j] = bs[out0 + r + 8 * j];
        bL1[j] = bs[128 + out0 + r + 8 * j];
    }
    // L2 swapped-layout biases: out = out20 + 8j + col2 + e
    float b2v[2][2];
    #pragma unroll
    for (int j = 0; j < 2; j++)
        #pragma unroll
        for (int e = 0; e < 2; e++)
            b2v[j][e] = bs[256 + 64 + out20 + 8 * j + col2 + e];

    // ---- lane-derived ldmatrix base addresses ----
    const int lA_k = (lane & 7) + ((lane & 16) ? 8 : 0);
    const int lA_c = (lane & 8) ? 8 : 0;
    const int lB_k = (lane & 7) + ((lane & 8) ? 8 : 0);
    const int lB_c = (lane & 16) ? 8 : 0;

    const uint32_t aW0 = sb + W0B + (uint32_t)(lA_k * kLDW + out0 + lA_c) * 2;
    const uint32_t aW1 = sb + W1B + (uint32_t)(lA_k * kLDW + out0 + lA_c) * 2;
    // L2 B operand: W2 via TRANS ldsm with B-pattern lanes ([k][out] memory)
    const uint32_t aW2n = sb + W2B + (uint32_t)(lB_k * kLDW2 + out20 + lB_c) * 2;
    const uint32_t aB0 = sb + X0B + (uint32_t)(lB_k * kLDX + px0 + lB_c) * 2;
    const uint32_t aB1 = sb + X1B + (uint32_t)(lB_k * kLDX + px0 + lB_c) * 2;

    // cooperative staging mapping (within group of 128 threads)
    const int s_ch = glt >> 3;                 // 0..15 (x8 strided)
    const int s_p4 = (glt & 7) * 4;            // px offset 0..28
    const int f_g  = glt >> 3;                 // FTL 4-ch group (glt < 64)

    __syncthreads();   // weights visible to all groups

    for (int t = blockIdx.x; t < kNTiles; t += gridDim.x) {
        const int b  = t >> 5;
        const int p0 = (t & 31) * kTP;
        const int useb = g_use[b];
        const int m    = g_midx[b];
        const int gpx  = p0 + px0 + s_p4;

        // ---- prefetch half the img slice BEFORE the barrier (regs only) ----
        const float* ibase = img + (size_t)(b * 64) * kHW + gpx;
        float4 pf0 = *(const float4*)(ibase + (size_t)s_ch * kHW);
        float4 pf1 = *(const float4*)(ibase + (size_t)(16 + s_ch) * kHW);

        GBAR(pg);   // S1: this group's prior-tile L2 done reading xs0

        // ---- cooperative staging of 128ch x 32px slice ----
        {
            __half* xbase = xs0 + px0 + s_p4;
            st_half4(xbase + (64 + s_ch) * kLDX, pf0.x, pf0.y, pf0.z, pf0.w);
            st_half4(xbase + (80 + s_ch) * kLDX, pf1.x, pf1.y, pf1.z, pf1.w);
            #pragma unroll
            for (int n = 2; n < 4; n++) {
                float4 v = *(const float4*)(ibase + (size_t)(16 * n + s_ch) * kHW);
                st_half4(xbase + (64 + 16 * n + s_ch) * kLDX, v.x, v.y, v.z, v.w);
            }
            if (useb) {
                const float* mbase = mem + (size_t)(m * 64) * kHW + gpx;
                #pragma unroll
                for (int n = 0; n < 2; n++) {          // mem ch 32..63
                    float4 v = *(const float4*)(mbase
                                + (size_t)(32 + 16 * n + s_ch) * kHW);
                    st_half4(xbase + (32 + 16 * n + s_ch) * kLDX,
                             v.x, v.y, v.z, v.w);
                }
                if (glt < 64) {                        // FTL ch 0..31
                    float xfv[16];
                    #pragma unroll
                    for (int j = 0; j < 16; j++) xfv[j] = g_xf[b * 16 + j];
                    const float* mp = mbase + (size_t)(4 * f_g) * kHW;
                    float4 v0 = *(const float4*)(mp);
                    float4 v1 = *(const float4*)(mp + kHW);
                    float4 v2 = *(const float4*)(mp + 2 * kHW);
                    float4 v3 = *(const float4*)(mp + 3 * kHW);
                    __half* xg = xbase + (4 * f_g) * kLDX;
                    #pragma unroll
                    for (int rr = 0; rr < 4; rr++) {
                        float a0 = xfv[rr*4+0], a1 = xfv[rr*4+1];
                        float a2 = xfv[rr*4+2], a3 = xfv[rr*4+3];
                        st_half4(xg + rr * kLDX,
                                 a0*v0.x + a1*v1.x + a2*v2.x + a3*v3.x,
                                 a0*v0.y + a1*v1.y + a2*v2.y + a3*v3.y,
                                 a0*v0.z + a1*v1.z + a2*v2.z + a3*v3.z,
                                 a0*v0.w + a1*v1.w + a2*v2.w + a3*v3.w);
                    }
                }
            }
        }
        GBAR(pg);   // S2: group's xs0 slice staged

        // ---- L0: read xs0, write xs1 (k-skip lower half when !useb) ----
        if (useb)
            layer_gemm32(aW0, aB0, 8, bL0, sb + X1B, out0, px0, r, col2);
        else
            layer_gemm32(aW0 + 64 * kLDW * 2, aB0 + 64 * kLDX * 2, 4,
                         bL0, sb + X1B, out0, px0, r, col2);
        GBAR(pg);   // S3

        // ---- L1: read xs1, write xs0 ----
        layer_gemm32(aW1, aB1, 8, bL1, sb + X0B, out0, px0, r, col2);
        GBAR(pg);   // S4

        // ---- L2 (swapped): A = X (px=M), B = W2 (out=N); coalesced STG ----
        {
            float c[2][2][4];                   // [pxfrag i][outfrag j]
            #pragma unroll
            for (int i = 0; i < 2; i++)
                #pragma unroll
                for (int j = 0; j < 2; j++)
                    #pragma unroll
                    for (int q = 0; q < 4; q++) c[i][j][q] = 0.f;

            uint32_t aX = aB0, aW = aW2n;
            #pragma unroll 4
            for (int k = 0; k < 8; k++) {
                uint32_t x0[4], x1[4], w[4];
                ldsm4t(x0, aX);                 // px 0..15 (A via perm)
                ldsm4t(x1, aX + 32);            // px 16..31
                ldsm4t(w, aW);                  // W2 B frags (TRANS — the fix)
                // A perm: {r0, r2, r1, r3}
                mma16816_p(c[0][0], x0[0], x0[2], x0[1], x0[3], w[0], w[1]);
                mma16816_p(c[0][1], x0[0], x0[2], x0[1], x0[3], w[2], w[3]);
                mma16816_p(c[1][0], x1[0], x1[2], x1[1], x1[3], w[0], w[1]);
                mma16816_p(c[1][1], x1[0], x1[2], x1[1], x1[3], w[2], w[3]);
                aX += 16 * kLDX * 2;
                aW += 16 * kLDW2 * 2;
            }
            // C(px,out): px = px0 + 16i + r (+8), out = out20 + 8j + col2 (+e)
            float* ob = out + (size_t)b * 64 * kHW + p0 + px0;
            #pragma unroll
            for (int i = 0; i < 2; i++)
                #pragma unroll
                for (int j = 0; j < 2; j++) {
                    float* p00 = ob + (size_t)(out20 + 8 * j + col2) * kHW
                               + 16 * i + r;
                    p00[0]               = c[i][j][0] + b2v[j][0];
                    p00[(size_t)kHW]     = c[i][j][1] + b2v[j][1];
                    p00[8]               = c[i][j][2] + b2v[j][0];
                    p00[(size_t)kHW + 8] = c[i][j][3] + b2v[j][1];
                }
        }
        // loop-head S1 guards xs0 restaging for this group
    }
}

// ---------------------------------------------------------------------------
extern "C" void kernel_launch(void* const* d_in, const int* in_sizes, int n_in,
                              void* d_out, int out_size) {
    const float* img      = (const float*)d_in[0];
    const float* mem      = (const float*)d_in[1];
    const float* prev_ext = (const float*)d_in[2];
    const float* cur_ext  = (const float*)d_in[3];
    const int*   midx     = (const int*)d_in[4];
    const unsigned char* use_raw = (const unsigned char*)d_in[5];
    const float* Ws       = (const float*)d_in[6];
    const float* bs       = (const float*)d_in[7];
    float*       out      = (float*)d_out;

    static int nsm = 0;
    if (nsm == 0) {
        int dev = 0;
        cudaGetDevice(&dev);
        cudaDeviceGetAttribute(&nsm, cudaDevAttrMultiProcessorCount, dev);
        if (nsm <= 0) nsm = 148;
        cudaFuncSetAttribute(fused_kernel,
                             cudaFuncAttributeMaxDynamicSharedMemorySize,
                             (int)SMEM_BYTES);
    }

    prep_kernel<<<1, 32>>>(prev_ext, cur_ext, midx, use_raw);
    fused_kernel<<<nsm, kTHREADS, SMEM_BYTES>>>(img, mem, Ws, bs, out);
}

// round 14
// speedup vs baseline: 1.0354x; 1.0354x over previous
#include <cuda_runtime.h>
#include <cuda_fp16.h>
#include <cstdint>
#include <math.h>

// ---------------------------------------------------------------------------
// SimpleConvRNN fused kernel for GB300 (sm_103a) — round 14.
// R11 (best: 66.9us) + XOR bank-swizzle on activation tiles:
//   physical px-offset = logical ^ (16 * (row & 1))   [32B chunk-pair swap]
// -> layer-epilogue st.b32 becomes bank-conflict-free (was 2-way),
//    ldsm B reads remain conflict-free. No steady-state instruction cost.
// ---------------------------------------------------------------------------

namespace {
constexpr int kB   = 32;
constexpr int kHW  = 6144;
constexpr int kTP  = 192;                   // pixels per tile (6 px-groups x 32)
constexpr int kTilesPerB = 32;
constexpr int kNTiles = kB * kTilesPerB;    // 1024
constexpr int kTHREADS = 768;

constexpr int kLDW  = 136;                  // W0/W1 pitch (halves)
constexpr int kLDW2 = 72;                   // W2 pitch (halves)
constexpr int kLDX  = 200;                  // xs pitch (halves)

constexpr int W0B = 0;
constexpr int W1B = W0B + 128 * kLDW * 2;   // 34816
constexpr int W2B = W1B + 128 * kLDW * 2;   // 69632
constexpr int X0B = W2B + 128 * kLDW2 * 2;  // 88064
constexpr int X1B = X0B + 128 * kLDX * 2;   // 139264
constexpr size_t SMEM_BYTES = X1B + 128 * kLDX * 2;  // 190464 B
}

__device__ __forceinline__ uint32_t smem_u32(const void* p) {
    uint32_t a;
    asm("{ .reg .u64 t; cvta.to.shared.u64 t, %1; cvt.u32.u64 %0, t; }"
        : "=r"(a) : "l"(p));
    return a;
}
__device__ __forceinline__ void ldsm4t(uint32_t* r, uint32_t addr) {
    asm volatile("ldmatrix.sync.aligned.m8n8.x4.trans.shared.b16 "
                 "{%0,%1,%2,%3}, [%4];"
                 : "=r"(r[0]), "=r"(r[1]), "=r"(r[2]), "=r"(r[3]) : "r"(addr));
}
__device__ __forceinline__ void mma16816(float c[4], const uint32_t* a,
                                         const uint32_t b0, const uint32_t b1) {
    asm volatile(
        "mma.sync.aligned.m16n8k16.row.col.f32.f16.f16.f32 "
        "{%0,%1,%2,%3}, {%4,%5,%6,%7}, {%8,%9}, {%0,%1,%2,%3};"
        : "+f"(c[0]), "+f"(c[1]), "+f"(c[2]), "+f"(c[3])
        : "r"(a[0]), "r"(a[1]), "r"(a[2]), "r"(a[3]), "r"(b0), "r"(b1));
}
__device__ __forceinline__ uint32_t h2pack(float a, float b) {
    __half2 h = __floats2half2_rn(a, b);
    return *(uint32_t*)&h;
}
__device__ __forceinline__ void st_half4(__half* p, float a, float b,
                                         float c, float d) {
    uint2 v;
    v.x = h2pack(a, b);
    v.y = h2pack(c, d);
    *(uint2*)p = v;
}
#define GBAR(pg) asm volatile("bar.sync %0, 128;" :: "r"(1 + (pg)) : "memory")

__device__ float g_xf[kB * 16];
__device__ int   g_use[kB];
__device__ int   g_midx[kB];

// ---------------------------------------------------------------------------
__global__ void prep_kernel(const float* __restrict__ prev_ext,
                            const float* __restrict__ cur_ext,
                            const int*   __restrict__ memory_idx,
                            const unsigned char* __restrict__ use_raw) {
    int b = threadIdx.x;
    if (b >= kB) return;

    const unsigned int* w32 = (const unsigned int*)use_raw;
    bool int_layout = true, float_layout = true;
    #pragma unroll
    for (int i = 0; i < 8; i++) {
        unsigned int v = w32[i];
        if (v != 0u && v != 1u)          int_layout = false;
        if (v != 0u && v != 0x3f800000u) float_layout = false;
    }
    int use;
    if (int_layout || float_layout) use = (w32[b] != 0u) ? 1 : 0;
    else                            use = use_raw[b] ? 1 : 0;
    g_use[b] = use;
    int m = memory_idx[b];
    g_midx[b] = m;

    float A[4][8];
    #pragma unroll
    for (int r = 0; r < 4; r++)
        #pragma unroll
        for (int c = 0; c < 4; c++) {
            A[r][c]     = use ? prev_ext[(size_t)m * 16 + r * 4 + c]
                              : (r == c ? 1.f : 0.f);
            A[r][c + 4] = (r == c) ? 1.f : 0.f;
        }
    for (int col = 0; col < 4; col++) {
        int piv = col;
        float best = fabsf(A[col][col]);
        for (int r = col + 1; r < 4; r++) {
            float v = fabsf(A[r][col]);
            if (v > best) { best = v; piv = r; }
        }
        if (piv != col)
            for (int j = 0; j < 8; j++) {
                float t = A[col][j]; A[col][j] = A[piv][j]; A[piv][j] = t;
            }
        float inv = 1.f / A[col][col];
        for (int j = 0; j < 8; j++) A[col][j] *= inv;
        for (int r = 0; r < 4; r++) {
            if (r == col) continue;
            float f = A[r][col];
            for (int j = 0; j < 8; j++) A[r][j] -= f * A[col][j];
        }
    }
    #pragma unroll
    for (int i = 0; i < 4; i++)
        #pragma unroll
        for (int j = 0; j < 4; j++) {
            float s = 0.f;
            #pragma unroll
            for (int k = 0; k < 4; k++)
                s += cur_ext[(size_t)b * 16 + i * 4 + k] * A[k][4 + j];
            g_xf[b * 16 + i * 4 + j] = s;
        }
}

// ---------------------------------------------------------------------------
// 32out x 32px layer slice, ksteps k-iterations. B-operand lane addresses aB
// (chunks 0/1 logical) and aBh (chunks 2/3 logical) are swizzle-resolved by
// the caller. Epilogue bias+relu+fp16 -> STS with parity swizzle.
__device__ __forceinline__ void layer_gemm32(
    uint32_t aW, uint32_t aB, uint32_t aBh, int ksteps, const float bl[4],
    uint32_t xw, int out0, int pxcol, int r, int col2)
{
    float c[8][4];
    #pragma unroll
    for (int i = 0; i < 8; i++)
        #pragma unroll
        for (int j = 0; j < 4; j++) c[i][j] = 0.f;

    #pragma unroll 4
    for (int k = 0; k < ksteps; k++) {
        uint32_t a0[4], a1[4], b0[4], b1[4];
        ldsm4t(a0, aW);
        ldsm4t(a1, aW + 32);
        ldsm4t(b0, aB);
        ldsm4t(b1, aBh);
        mma16816(c[0], a0, b0[0], b0[1]);
        mma16816(c[1], a0, b0[2], b0[3]);
        mma16816(c[2], a0, b1[0], b1[1]);
        mma16816(c[3], a0, b1[2], b1[3]);
        mma16816(c[4], a1, b0[0], b0[1]);
        mma16816(c[5], a1, b0[2], b0[3]);
        mma16816(c[6], a1, b1[0], b1[1]);
        mma16816(c[7], a1, b1[2], b1[3]);
        aW  += 16 * kLDW * 2;
        aB  += 16 * kLDX * 2;
        aBh += 16 * kLDX * 2;
    }

    // epilogue: rows out0+16f+r; parity = r&1 -> px-offset xor 16
    const int swz = (r & 1) << 4;
    #pragma unroll
    for (int f = 0; f < 2; f++) {
        float bhi = bl[2 * f], blo = bl[2 * f + 1];
        int row = out0 + 16 * f + r;
        #pragma unroll
        for (int p = 0; p < 4; p++) {
            const float* cc = c[f * 4 + p];
            uint32_t h01 = h2pack(fmaxf(cc[0] + bhi, 0.f),
                                  fmaxf(cc[1] + bhi, 0.f));
            uint32_t h23 = h2pack(fmaxf(cc[2] + blo, 0.f),
                                  fmaxf(cc[3] + blo, 0.f));
            int off = (8 * p + col2) ^ swz;
            uint32_t addr = xw + (uint32_t)(row * kLDX + pxcol + off) * 2;
            asm volatile("st.shared.b32 [%0], %1;" :: "r"(addr), "r"(h01));
            asm volatile("st.shared.b32 [%0], %1;"
                         :: "r"(addr + 8 * kLDX * 2), "r"(h23));
        }
    }
}

// ---------------------------------------------------------------------------
__global__ void __launch_bounds__(kTHREADS, 1)
fused_kernel(const float* __restrict__ img,
             const float* __restrict__ mem,
             const float* __restrict__ Ws,
             const float* __restrict__ bs,
             float* __restrict__ out) {
    extern __shared__ char smc[];
    const uint32_t sb = smem_u32(smc);
    __half* W0h = (__half*)(smc + W0B);
    __half* W1h = (__half*)(smc + W1B);
    __half* W2h = (__half*)(smc + W2B);
    __half* xs0 = (__half*)(smc + X0B);

    const int tid  = threadIdx.x;
    const int wid  = tid >> 5;
    const int lane = tid & 31;
    const int r    = lane >> 2;
    const int col2 = (lane & 3) * 2;

    // ---- one-time weight staging (transposed [k][out], fp16) ----
    for (int i = tid; i < 128 * 128; i += kTHREADS) {
        int o = i >> 7, k = i & 127;
        W0h[k * kLDW + o] = __float2half_rn(Ws[o * 128 + k]);
        W1h[k * kLDW + o] = __float2half_rn(Ws[16384 + o * 128 + k]);
    }
    for (int i = tid; i < 64 * 128; i += kTHREADS) {
        int o = i >> 7, k = i & 127;
        W2h[k * kLDW2 + o] = __float2half_rn(Ws[2 * 16384 + (64 + o) * 128 + k]);
    }

    // ---- warp tiling: og = out-group (32 ch), pg = px-group (32 px) ----
    const int og    = wid & 3;
    const int pg    = wid >> 2;                // 0..5
    const int out0  = og * 32;
    const int px0   = pg * 32;
    const int out20 = og * 16;
    float bL0[4], bL1[4], bL2[2];
    #pragma unroll
    for (int j = 0; j < 4; j++) {
        bL0[j] = bs[out0 + r + 8 * j];
        bL1[j] = bs[128 + out0 + r + 8 * j];
    }
    bL2[0] = bs[256 + 64 + out20 + r];
    bL2[1] = bs[256 + 64 + out20 + r + 8];

    // ---- lane-derived ldmatrix base addresses ----
    const int lA_k = (lane & 7) + ((lane & 16) ? 8 : 0);
    const int lA_c = (lane & 8) ? 8 : 0;
    const int lB_k = (lane & 7) + ((lane & 8) ? 8 : 0);
    const int lB_c = (lane & 16) ? 8 : 0;
    const int swzB = (lB_k & 1) << 4;          // xs swizzle for this lane's row

    const uint32_t aW0 = sb + W0B + (uint32_t)(lA_k * kLDW + out0 + lA_c) * 2;
    const uint32_t aW1 = sb + W1B + (uint32_t)(lA_k * kLDW + out0 + lA_c) * 2;
    const uint32_t aW2 = sb + W2B + (uint32_t)(lA_k * kLDW2 + out20 + lA_c) * 2;
    // B operands on xs: logical chunks {0,1} (lo) and {2,3} (hi), swizzled
    const uint32_t aB0  = sb + X0B +
        (uint32_t)(lB_k * kLDX + px0 + (lB_c ^ swzB)) * 2;
    const uint32_t aB0h = sb + X0B +
        (uint32_t)(lB_k * kLDX + px0 + ((lB_c + 16) ^ swzB)) * 2;
    const uint32_t aB1  = sb + X1B +
        (uint32_t)(lB_k * kLDX + px0 + (lB_c ^ swzB)) * 2;
    const uint32_t aB1h = sb + X1B +
        (uint32_t)(lB_k * kLDX + px0 + ((lB_c + 16) ^ swzB)) * 2;

    // staging lane mapping: 4 px per lane, 8 channels per lane
    const int spx = (lane & 7) << 2;           // px offset within group: 0..28
    const int sch = (lane >> 3) << 3;          // ch offset within 32: 0,8,16,24
    const int spx0 = spx;                      // even-row physical offset
    const int spx1 = spx ^ 16;                 // odd-row physical offset

    __syncthreads();   // weights visible to all groups

    for (int t = blockIdx.x; t < kNTiles; t += gridDim.x) {
        const int b  = t >> 5;
        const int p0 = (t & 31) * kTP;
        const int useb = g_use[b];
        const int m    = g_midx[b];

        GBAR(pg);   // S1: this group's prior-tile L2 done reading xs0

        // ---- stage this warp's 32ch x 32px slice into xs0 (swizzled) ----
        if (og >= 2) {                                         // img channels
            const int gpx = p0 + px0 + spx;
            const int rowb = 64 + (og - 2) * 32 + sch;         // even
            __half* xd = xs0 + rowb * kLDX + px0;
            const float* base =
                img + (size_t)(b * 64 + (og - 2) * 32 + sch) * kHW + gpx;
            #pragma unroll
            for (int c = 0; c < 8; c++) {
                float4 v = *(const float4*)(base + (size_t)c * kHW);
                st_half4(xd + c * kLDX + ((c & 1) ? spx1 : spx0),
                         v.x, v.y, v.z, v.w);
            }
        } else if (useb) {
            const int gpx = p0 + px0 + spx;
            if (og == 1) {                                     // mem ch 32..63
                const int rowb = 32 + sch;                     // even
                __half* xd = xs0 + rowb * kLDX + px0;
                const float* base =
                    mem + (size_t)(m * 64 + 32 + sch) * kHW + gpx;
                #pragma unroll
                for (int c = 0; c < 8; c++) {
                    float4 v = *(const float4*)(base + (size_t)c * kHW);
                    st_half4(xd + c * kLDX + ((c & 1) ? spx1 : spx0),
                             v.x, v.y, v.z, v.w);
                }
            } else {                                           // FTL ch 0..31
                float xfv[16];
                #pragma unroll
                for (int j = 0; j < 16; j++) xfv[j] = g_xf[b * 16 + j];
                #pragma unroll
                for (int gi = 0; gi < 2; gi++) {
                    int g = (sch >> 2) + gi;                   // 4-ch group 0..7
                    const float* mp =
                        mem + (size_t)(m * 64 + 4 * g) * kHW + gpx;
                    float4 v0 = *(const float4*)(mp);
                    float4 v1 = *(const float4*)(mp + kHW);
                    float4 v2 = *(const float4*)(mp + 2 * kHW);
                    float4 v3 = *(const float4*)(mp + 3 * kHW);
                    __half* xg = xs0 + (4 * g) * kLDX + px0;   // row 4g even
                    #pragma unroll
                    for (int rr = 0; rr < 4; rr++) {
                        float a0 = xfv[rr*4+0], a1 = xfv[rr*4+1];
                        float a2 = xfv[rr*4+2], a3 = xfv[rr*4+3];
                        st_half4(xg + rr * kLDX + ((rr & 1) ? spx1 : spx0),
                                 a0*v0.x + a1*v1.x + a2*v2.x + a3*v3.x,
                                 a0*v0.y + a1*v1.y + a2*v2.y + a3*v3.y,
                                 a0*v0.z + a1*v1.z + a2*v2.z + a3*v3.z,
                                 a0*v0.w + a1*v1.w + a2*v2.w + a3*v3.w);
                    }
                }
            }
        }
        GBAR(pg);   // S2: group's xs0 slice staged

        // ---- L0: read xs0, write xs1 (k-skip lower half when !useb) ----
        if (useb)
            layer_gemm32(aW0, aB0, aB0h, 8, bL0, sb + X1B, out0, px0, r, col2);
        else
            layer_gemm32(aW0 + 64 * kLDW * 2,
                         aB0 + 64 * kLDX * 2, aB0h + 64 * kLDX * 2, 4,
                         bL0, sb + X1B, out0, px0, r, col2);
        GBAR(pg);   // S3

        // ---- L1: read xs1, write xs0 ----
        layer_gemm32(aW1, aB1, aB1h, 8, bL1, sb + X0B, out0, px0, r, col2);
        GBAR(pg);   // S4

        // ---- L2: read xs0, 16out x 32px, straight to gmem ----
        {
            float c[4][4];
            #pragma unroll
            for (int i = 0; i < 4; i++)
                #pragma unroll
                for (int j = 0; j < 4; j++) c[i][j] = 0.f;

            uint32_t aA = aW2, aB = aB0, aBh = aB0h;
            #pragma unroll 4
            for (int k = 0; k < 8; k++) {
                uint32_t a0[4], b0[4], b1[4];
                ldsm4t(a0, aA);
                ldsm4t(b0, aB);
                ldsm4t(b1, aBh);
                mma16816(c[0], a0, b0[0], b0[1]);
                mma16816(c[1], a0, b0[2], b0[3]);
                mma16816(c[2], a0, b1[0], b1[1]);
                mma16816(c[3], a0, b1[2], b1[3]);
                aA  += 16 * kLDW2 * 2;
                aB  += 16 * kLDX * 2;
                aBh += 16 * kLDX * 2;
            }
            float* obase = out + (size_t)(b * 64 + out20 + r) * kHW
                         + p0 + px0 + col2;
            #pragma unroll
            for (int p = 0; p < 4; p++) {
                float2 v01 = make_float2(c[p][0] + bL2[0], c[p][1] + bL2[0]);
                float2 v23 = make_float2(c[p][2] + bL2[1], c[p][3] + bL2[1]);
                *(float2*)(obase + 8 * p)                   = v01;
                *(float2*)(obase + 8 * p + (size_t)8 * kHW) = v23;
            }
        }
        // loop-head S1 guards xs0 restaging for this group
    }
}

// ---------------------------------------------------------------------------
extern "C" void kernel_launch(void* const* d_in, const int* in_sizes, int n_in,
                              void* d_out, int out_size) {
    const float* img      = (const float*)d_in[0];
    const float* mem      = (const float*)d_in[1];
    const float* prev_ext = (const float*)d_in[2];
    const float* cur_ext  = (const float*)d_in[3];
    const int*   midx     = (const int*)d_in[4];
    const unsigned char* use_raw = (const unsigned char*)d_in[5];
    const float* Ws       = (const float*)d_in[6];
    const float* bs       = (const float*)d_in[7];
    float*       out      = (float*)d_out;

    static int nsm = 0;
    if (nsm == 0) {
        int dev = 0;
        cudaGetDevice(&dev);
        cudaDeviceGetAttribute(&nsm, cudaDevAttrMultiProcessorCount, dev);
        if (nsm <= 0) nsm = 148;
        cudaFuncSetAttribute(fused_kernel,
                             cudaFuncAttributeMaxDynamicSharedMemorySize,
                             (int)SMEM_BYTES);
    }

    prep_kernel<<<1, 32>>>(prev_ext, cur_ext, midx, use_raw);
    fused_kernel<<<nsm, kTHREADS, SMEM_BYTES>>>(img, mem, Ws, bs, out);
}